// round 13
// baseline (speedup 1.0000x reference)
#include <cuda_runtime.h>
#include <math.h>

#define BB 16
#define T2 2048
#define T1 512
#define FF 128
#define NBT (BB*T2)
#define TS 8   // phonemes per k3 block

// scratch (allocation-free rule: __device__ globals)
__device__ float g_prop[NBT];
__device__ float g_nrm[NBT];
__device__ float g_crs[NBT];
__device__ float g_imv[NBT];   // monotone (pre-mask) imv

__device__ __forceinline__ float warpsumf(float v) {
#pragma unroll
    for (int o = 16; o > 0; o >>= 1) v += __shfl_down_sync(0xffffffffu, v, o);
    return v;
}

// ---------------------------------------------------------------------------
// k1: warp per (b,t) row; 8 rows/block share mels via smem.
// Barrier is EARLY (right after the tiny mels store) so the long alpha
// stream runs un-barriered afterwards. Pure fp32.
//  prop[r] = sum_s alpha[r,s]*s   (64 MB streaming read — dominant)
//  nrm[r]  = ||mels[r,:]||
//  crs[r]  = dot(mels[r,:], mels[r+1,:]) for t < T2-1
// ---------------------------------------------------------------------------
__global__ void __launch_bounds__(256) k1(const float* __restrict__ mels,
                                          const float* __restrict__ alpha) {
    int w    = threadIdx.x >> 5;
    int lane = threadIdx.x & 31;
    int row  = blockIdx.x * 8 + w;       // NBT % 8 == 0, T2 % 8 == 0
    int t    = row % T2;

    __shared__ float4 s_mel[8 * 32];

    // 1) tiny mels load + share (1 LDG.128 per thread), then one early barrier
    const float4* M = reinterpret_cast<const float4*>(mels + (size_t)row * FF);
    float4 m = M[lane];
    s_mel[w * 32 + lane] = m;
    __syncthreads();

    // 2) long alpha stream (16 LDG.128 per thread), evict-first
    const float4* A = reinterpret_cast<const float4*>(alpha + (size_t)row * T1);
    float ps = 0.f;
#pragma unroll
    for (int j = 0; j < 4; j++) {
        int i4 = j * 32 + lane;
        float4 a = __ldcs(&A[i4]);
        float base = (float)(i4 * 4);
        ps += a.x * base + a.y * (base + 1.f) + a.z * (base + 2.f) + a.w * (base + 3.f);
    }

    // 3) norms + cross-row dot from smem (last warp fetches row+1 from L2)
    float ns = m.x * m.x + m.y * m.y + m.z * m.z + m.w * m.w;
    float cs = 0.f;
    bool has_next = (t < T2 - 1);
    if (has_next) {
        float4 m2 = (w < 7) ? s_mel[(w + 1) * 32 + lane] : M[32 + lane];
        cs = m.x * m2.x + m.y * m2.y + m.z * m2.z + m.w * m2.w;
    }
    ps = warpsumf(ps);
    ns = warpsumf(ns);
    cs = warpsumf(cs);
    if (lane == 0) {
        g_prop[row] = ps;
        g_nrm[row]  = sqrtf(ns);
        if (has_next) g_crs[row] = cs;
    }
}

// ---------------------------------------------------------------------------
// k2: one block per batch. activity -> eff_delta -> double block scan ->
// rescale -> imv (output + monotone scratch).
// ---------------------------------------------------------------------------
__global__ void __launch_bounds__(256) k2(const int* __restrict__ mel_mask,
                                          const int* __restrict__ text_mask,
                                          float* __restrict__ imv_out) {
    const int PER = T2 / 256;  // 8
    int b = blockIdx.x;
    int tid = threadIdx.x;

    __shared__ double s_sum[256];
    __shared__ int s_amcnt, s_tmcnt;
    __shared__ double s_scale;
    __shared__ double s_last;
    if (tid == 0) { s_amcnt = 0; s_tmcnt = 0; }
    __syncthreads();

    const float* prop = g_prop + b * T2;
    const float* nrm  = g_nrm  + b * T2;
    const float* crs  = g_crs  + b * T2;
    const int* am = mel_mask  + b * T2;
    const int* tm = text_mask + b * T1;

    double v[PER];
    double local = 0.0;
    int amc = 0;
    int base = tid * PER;
#pragma unroll
    for (int i = 0; i < PER; i++) {
        int t = base + i;
        int a = am[t];
        amc += a;
        float eff = 0.f;
        if (t > 0 && a) {
            float cosv = crs[t - 1] / (fmaxf(nrm[t - 1], 1e-12f) * fmaxf(nrm[t], 1e-12f));
            float act = 1.f / (1.f + __expf(-10.f * (0.9f - cosv)));
            float d = prop[t] - prop[t - 1];
            eff = fminf(fmaxf(d * act, 0.f), 1.f);
        }
        local += (double)eff;
        v[i] = local;  // inclusive within thread
    }
    s_sum[tid] = local;
    atomicAdd(&s_amcnt, amc);
    atomicAdd(&s_tmcnt, tm[tid] + tm[tid + 256]);
    __syncthreads();

    // Hillis-Steele inclusive scan over thread totals (double)
    for (int off = 1; off < 256; off <<= 1) {
        double x = (tid >= off) ? s_sum[tid - off] : 0.0;
        __syncthreads();
        s_sum[tid] += x;
        __syncthreads();
    }
    double excl = s_sum[tid] - local;

    // raw value at last valid index (owned by exactly one thread)
    {
        int last = max(s_amcnt - 1, 0);
        if (last >= base && last < base + PER)
            s_last = (excl + v[last - base]) * (double)am[last];
    }
    __syncthreads();
    if (tid == 0) {
        double lastval = fmax(s_last, 1e-6);
        s_scale = fmax((double)s_tmcnt - 1.0, 0.0) / lastval;
    }
    __syncthreads();
    double scale = s_scale;

#pragma unroll
    for (int i = 0; i < PER; i++) {
        int t = base + i;
        float iv = (float)((excl + v[i]) * scale);   // monotone
        g_imv[b * T2 + t] = iv;
        imv_out[b * T2 + t] = iv * (float)am[t];
    }
}

// ---------------------------------------------------------------------------
// k3: block per (b, 8-phoneme tile), 128 threads.
// Phase A (thread-per-frame): <=8 window exps ONCE into regs -> Z -> map to
// TS slots; durations via shared atomicAdd.
// Phase B (thread-per-feature): acc[k] += w * mels[t,f].
// ---------------------------------------------------------------------------
__global__ void __launch_bounds__(FF) k3(const float* __restrict__ mels,
                                         const int* __restrict__ mel_mask,
                                         const int* __restrict__ text_mask,
                                         float* __restrict__ aligned,
                                         float* __restrict__ durations) {
    int b  = blockIdx.y;
    int sb = blockIdx.x * TS;
    int f  = threadIdx.x;

    const float* iv = g_imv + b * T2;
    __shared__ int s_lo, s_hi;
    __shared__ float s_w[TS * 128];
    __shared__ float s_dur[TS];

    if (f == 0) {
        // union window: iv in [sb-4.5, sb+TS-1+4.5] covers every (t,s) member
        float lob = (float)sb - 4.5f;
        float hib = (float)(sb + TS - 1) + 4.5f;
        int l = 0, r = T2;
        while (l < r) { int mm = (l + r) >> 1; if (iv[mm] < lob) l = mm + 1; else r = mm; }
        int lo = l;
        r = T2;
        while (l < r) { int mm = (l + r) >> 1; if (iv[mm] <= hib) l = mm + 1; else r = mm; }
        s_lo = lo; s_hi = l;
    }
    if (f < TS) s_dur[f] = 0.f;
    __syncthreads();
    int lo = s_lo, hi = s_hi;

    const int*   am = mel_mask + b * T2;
    const int*   tm = text_mask + b * T1;
    const float* mcol = mels + ((size_t)b * T2) * FF + f;

    float acc[TS];
#pragma unroll
    for (int k = 0; k < TS; k++) acc[k] = 0.f;

    for (int c0 = lo; c0 < hi; c0 += 128) {
        int t = c0 + f;
        float w[TS];
#pragma unroll
        for (int k = 0; k < TS; k++) w[k] = 0.f;

        if (t < hi && am[t]) {
            float v = iv[t];
            int fi = (int)floorf(v);
            int s0 = max(0, fi - 3);
            int s1 = min(T1 - 1, fi + 4);
            // window exponentials computed ONCE
            float e[8];
            float Z = 0.f;
#pragma unroll
            for (int j = 0; j < 8; j++) {
                int s = s0 + j;
                float ej = 0.f;
                if (s <= s1 && tm[s]) {
                    float dd = v - (float)s;
                    ej = __expf(-10.f * dd * dd);
                }
                e[j] = ej;
                Z += ej;
            }
            if (Z > 0.f) {
                float rz = 1.f / Z;
#pragma unroll
                for (int j = 0; j < 8; j++) {
                    int k = (s0 + j) - sb;
                    if (k >= 0 && k < TS && e[j] > 0.f) {
                        float wv = e[j] * rz;
                        w[k] = wv;
                        atomicAdd(&s_dur[k], wv);
                    }
                }
            }
        }
#pragma unroll
        for (int k = 0; k < TS; k++) s_w[k * 128 + f] = w[k];
        __syncthreads();

        int n = min(hi - c0, 128);
        int nfull = n & ~7;
        for (int tt = 0; tt < nfull; tt += 8) {
            float mv[8];
#pragma unroll
            for (int u = 0; u < 8; u++)
                mv[u] = mcol[(size_t)(c0 + tt + u) * FF];   // batched loads -> MLP
#pragma unroll
            for (int u = 0; u < 8; u++) {
#pragma unroll
                for (int k = 0; k < TS; k++)
                    acc[k] += s_w[k * 128 + tt + u] * mv[u]; // broadcast LDS
            }
        }
        for (int tt = nfull; tt < n; tt++) {
            float mval = mcol[(size_t)(c0 + tt) * FF];
#pragma unroll
            for (int k = 0; k < TS; k++)
                acc[k] += s_w[k * 128 + tt] * mval;
        }
        __syncthreads();
    }

#pragma unroll
    for (int k = 0; k < TS; k++) {
        int s = sb + k;
        float d = s_dur[k];
        aligned[((size_t)(b * T1 + s)) * FF + f] = acc[k] / (d + 1e-8f);
        if (f == k) durations[b * T1 + s] = d;
    }
}

// ---------------------------------------------------------------------------
extern "C" void kernel_launch(void* const* d_in, const int* in_sizes, int n_in,
                              void* d_out, int out_size) {
    const float* mels      = (const float*)d_in[0];
    const float* alpha     = (const float*)d_in[1];
    const int*   mel_mask  = (const int*)d_in[2];
    const int*   text_mask = (const int*)d_in[3];

    float* aligned   = (float*)d_out;
    float* durations = aligned + (size_t)BB * T1 * FF;
    float* imv_out   = durations + (size_t)BB * T1;

    k1<<<NBT / 8, 256>>>(mels, alpha);
    k2<<<BB, 256>>>(mel_mask, text_mask, imv_out);
    dim3 g3(T1 / TS, BB);
    k3<<<g3, FF>>>(mels, mel_mask, text_mask, aligned, durations);
}